// round 2
// baseline (speedup 1.0000x reference)
#include <cuda_runtime.h>

#define B_   2
#define C_   64
#define H_   192
#define W_   192
#define HW_  (H_*W_)
#define O_   64
#define K_   9
#define J_   576          // C_*K_
#define EPS_ 1e-5f

// ---------------- scratch (no allocations allowed) ----------------
__device__ float g_xnhwc[B_*HW_*C_];   // x transposed to [B][H][W][C]
__device__ float g_off[B_*HW_*27];     // per pixel: dy[9], dx[9], mask[9]
__device__ float g_wt[J_*O_];          // dcn_w transposed: [j = k*64+c][o]

// ---------------- kernel 0: NCHW -> NHWC transpose ----------------
__global__ void k_transpose(const float* __restrict__ x) {
    __shared__ float t[32][33];
    int xt = blockIdx.x % (W_/32);
    int ct = blockIdx.x / (W_/32);
    int y  = blockIdx.y, b = blockIdx.z;
    int tx = threadIdx.x, ty = threadIdx.y;
#pragma unroll
    for (int i = 0; i < 4; i++) {
        int c  = ct*32 + ty + i*8;
        int xx = xt*32 + tx;
        t[ty + i*8][tx] = x[((b*C_ + c)*H_ + y)*W_ + xx];
    }
    __syncthreads();
#pragma unroll
    for (int i = 0; i < 4; i++) {
        int xx = xt*32 + ty + i*8;
        int c  = ct*32 + tx;
        g_xnhwc[(((b*H_ + y)*W_ + xx) << 6) + c] = t[tx][ty + i*8];
    }
}

// ---------------- kernel 1: transpose dcn_w -> [j][o] ----------------
__global__ void k_wprep(const float* __restrict__ dcn_w) {
    int t = blockIdx.x*256 + threadIdx.x;     // t = j*64 + o
    if (t < J_*O_) {
        int o = t & 63;
        int j = t >> 6;
        int c = j & 63;
        int k = j >> 6;
        g_wt[t] = dcn_w[o*J_ + c*K_ + k];
    }
}

// ------- kernel 2: dwconv + BN + ReLU + 1x1 -> offsets / mask -------
__global__ void __launch_bounds__(256) k_offsets(
    const float* __restrict__ dw_w, const float* __restrict__ dw_b,
    const float* __restrict__ bn_g, const float* __restrict__ bn_b,
    const float* __restrict__ bn_m, const float* __restrict__ bn_v,
    const float* __restrict__ pw_w, const float* __restrict__ pw_b)
{
    __shared__ float h_s[4*64];
    int tid = threadIdx.x;
    int sub = tid >> 6;            // pixel within block (4 per block)
    int c   = tid & 63;            // channel
    int gp  = blockIdx.x*4 + sub;
    int b   = gp / HW_;
    int rem = gp % HW_;
    int y   = rem / W_;
    int x   = rem % W_;

    float acc = 0.f;
#pragma unroll
    for (int ky = 0; ky < 3; ky++) {
        int yy = y + ky - 1;
        if ((unsigned)yy < H_) {
#pragma unroll
            for (int kx = 0; kx < 3; kx++) {
                int xx = x + kx - 1;
                if ((unsigned)xx < W_)
                    acc += dw_w[c*9 + ky*3 + kx]
                         * g_xnhwc[(((b*H_ + yy)*W_ + xx) << 6) + c];
            }
        }
    }
    float s = bn_g[c] * rsqrtf(bn_v[c] + EPS_);
    float h = fmaxf((acc + dw_b[c] - bn_m[c]) * s + bn_b[c], 0.f);
    h_s[tid] = h;
    __syncthreads();

    if (c < 27) {
        float om = pw_b[c];
        const float* pr = pw_w + c*64;
        const float* hh = h_s + sub*64;
#pragma unroll
        for (int i = 0; i < 64; i++) om += hh[i] * pr[i];

        float* ob = g_off + gp*27;
        if (c < 18) {
            // channel = k*2 + d ; d==0 -> dy (slot k), d==1 -> dx (slot 9+k)
            ob[(c & 1)*9 + (c >> 1)] = om;
        } else {
            ob[c] = 1.f / (1.f + expf(-om));   // mask slot 18..26
        }
    }
}

// ------- kernel 3: deformable gather + 64x576 projection -------
#define TP 32
#define SMEM_FLOATS (TP*J_ + 64*33)            // val tile + scratch(W tile / out staging)
#define SMEM_BYTES  (SMEM_FLOATS*4)

__global__ void __launch_bounds__(256) k_main(float* __restrict__ out) {
    extern __shared__ __align__(16) float sm[];
    float* val_s = sm;              // [32][576]
    float* scr   = sm + TP*J_;      // 2112 floats: W tile (2048) / out staging (64*33)

    int tid  = threadIdx.x;
    int gp0  = blockIdx.x * TP;
    int b    = gp0 / HW_;
    int rem0 = gp0 % HW_;
    int y    = rem0 / W_;           // one row per block (W=192 % 32 == 0)
    int x0   = rem0 % W_;

    // ---------- gather phase: build val[p][k*64+c] ----------
    {
        int p  = tid >> 3;          // pixel 0..31
        int c8 = (tid & 7) << 3;    // channel base, 8 channels per thread
        int xx = x0 + p;
        const float* ob = g_off + (gp0 + p)*27;
#pragma unroll
        for (int k = 0; k < 9; k++) {
            float dy = ob[k], dx = ob[9+k], m = ob[18+k];
            float py = (float)(y  + k/3 - 1) + dy;
            float px = (float)(xx + k%3 - 1) + dx;
            float fy0 = floorf(py), fx0 = floorf(px);
            float wy1 = py - fy0,   wx1 = px - fx0;
            float wy0 = 1.f - wy1,  wx0 = 1.f - wx1;
            int   iy  = (int)fy0,   ix  = (int)fx0;

            float wts[4] = { wy0*wx0, wy0*wx1, wy1*wx0, wy1*wx1 };
            int   ys[4]  = { iy, iy, iy+1, iy+1 };
            int   xs[4]  = { ix, ix+1, ix, ix+1 };

            float4 a0 = make_float4(0.f,0.f,0.f,0.f);
            float4 a1 = make_float4(0.f,0.f,0.f,0.f);
#pragma unroll
            for (int cn = 0; cn < 4; cn++) {
                if ((unsigned)ys[cn] < H_ && (unsigned)xs[cn] < W_) {
                    const float4* src = (const float4*)
                        (g_xnhwc + (((b*H_ + ys[cn])*W_ + xs[cn]) << 6) + c8);
                    float4 v0 = src[0], v1 = src[1];
                    float w = wts[cn];
                    a0.x += w*v0.x; a0.y += w*v0.y; a0.z += w*v0.z; a0.w += w*v0.w;
                    a1.x += w*v1.x; a1.y += w*v1.y; a1.z += w*v1.z; a1.w += w*v1.w;
                }
            }
            a0.x *= m; a0.y *= m; a0.z *= m; a0.w *= m;
            a1.x *= m; a1.y *= m; a1.z *= m; a1.w *= m;
            float4* dst = (float4*)(val_s + p*J_ + k*64 + c8);
            dst[0] = a0; dst[1] = a1;
        }
    }
    __syncthreads();

    // ---------- GEMM phase: out[p][o] = sum_j val[p][j] * Wt[j][o] ----------
    int lane = tid & 31;
    int warp = tid >> 5;
    int p0   = warp << 2;           // 4 pixels per warp
    float acc00=0.f, acc01=0.f, acc10=0.f, acc11=0.f;
    float acc20=0.f, acc21=0.f, acc30=0.f, acc31=0.f;

    const float* vb0 = val_s + (p0+0)*J_;
    const float* vb1 = val_s + (p0+1)*J_;
    const float* vb2 = val_s + (p0+2)*J_;
    const float* vb3 = val_s + (p0+3)*J_;

    for (int jt = 0; jt < 18; jt++) {          // 18 tiles of 32 j
        __syncthreads();                       // scr free to overwrite
        {
            float4* wdst = (float4*)scr;
            const float4* wsrc = (const float4*)(g_wt + jt*32*64);
            wdst[tid]       = wsrc[tid];
            wdst[tid + 256] = wsrc[tid + 256];
        }
        __syncthreads();

        const float* vt0 = vb0 + jt*32;
        const float* vt1 = vb1 + jt*32;
        const float* vt2 = vb2 + jt*32;
        const float* vt3 = vb3 + jt*32;
#pragma unroll
        for (int q = 0; q < 8; q++) {
            float4 v0 = *(const float4*)(vt0 + q*4);
            float4 v1 = *(const float4*)(vt1 + q*4);
            float4 v2 = *(const float4*)(vt2 + q*4);
            float4 v3 = *(const float4*)(vt3 + q*4);
            const float* wq = scr + q*256;     // (q*4+u)*64
            {   float w0 = wq[lane],       w1 = wq[lane+32];
                acc00 += v0.x*w0; acc01 += v0.x*w1;
                acc10 += v1.x*w0; acc11 += v1.x*w1;
                acc20 += v2.x*w0; acc21 += v2.x*w1;
                acc30 += v3.x*w0; acc31 += v3.x*w1; }
            {   float w0 = wq[64+lane],    w1 = wq[64+lane+32];
                acc00 += v0.y*w0; acc01 += v0.y*w1;
                acc10 += v1.y*w0; acc11 += v1.y*w1;
                acc20 += v2.y*w0; acc21 += v2.y*w1;
                acc30 += v3.y*w0; acc31 += v3.y*w1; }
            {   float w0 = wq[128+lane],   w1 = wq[128+lane+32];
                acc00 += v0.z*w0; acc01 += v0.z*w1;
                acc10 += v1.z*w0; acc11 += v1.z*w1;
                acc20 += v2.z*w0; acc21 += v2.z*w1;
                acc30 += v3.z*w0; acc31 += v3.z*w1; }
            {   float w0 = wq[192+lane],   w1 = wq[192+lane+32];
                acc00 += v0.w*w0; acc01 += v0.w*w1;
                acc10 += v1.w*w0; acc11 += v1.w*w1;
                acc20 += v2.w*w0; acc21 += v2.w*w1;
                acc30 += v3.w*w0; acc31 += v3.w*w1; }
        }
    }

    __syncthreads();
    // stage outputs [o][p] (stride 33, conflict-free), then coalesced store
    {
        int o0 = lane, o1 = lane + 32;
        scr[o0*33 + p0+0] = acc00; scr[o0*33 + p0+1] = acc10;
        scr[o0*33 + p0+2] = acc20; scr[o0*33 + p0+3] = acc30;
        scr[o1*33 + p0+0] = acc01; scr[o1*33 + p0+1] = acc11;
        scr[o1*33 + p0+2] = acc21; scr[o1*33 + p0+3] = acc31;
    }
    __syncthreads();
#pragma unroll
    for (int r = 0; r < 8; r++) {
        int q = r*256 + tid;
        int o = q >> 5;
        int p = q & 31;
        out[(b*O_ + o)*HW_ + rem0 + p] = scr[o*33 + p];
    }
}

// ------- kernel 4: per-(b,o) instance norm + ReLU, in-place -------
__global__ void __launch_bounds__(256) k_inorm(float* __restrict__ out) {
    int bo = blockIdx.x;
    float4* row = (float4*)(out + bo*HW_);
    float s = 0.f, ss = 0.f;
    for (int i = threadIdx.x; i < HW_/4; i += 256) {
        float4 v = row[i];
        s  += v.x + v.y + v.z + v.w;
        ss += v.x*v.x + v.y*v.y + v.z*v.z + v.w*v.w;
    }
#pragma unroll
    for (int off = 16; off; off >>= 1) {
        s  += __shfl_xor_sync(~0u, s,  off);
        ss += __shfl_xor_sync(~0u, ss, off);
    }
    __shared__ float rs[8], rss[8];
    __shared__ float mu_s, rstd_s;
    if ((threadIdx.x & 31) == 0) { rs[threadIdx.x>>5] = s; rss[threadIdx.x>>5] = ss; }
    __syncthreads();
    if (threadIdx.x == 0) {
        float S = 0.f, SS = 0.f;
#pragma unroll
        for (int i = 0; i < 8; i++) { S += rs[i]; SS += rss[i]; }
        float mu  = S / (float)HW_;
        float var = SS / (float)HW_ - mu*mu;
        mu_s = mu;
        rstd_s = rsqrtf(var + EPS_);
    }
    __syncthreads();
    float mu = mu_s, rstd = rstd_s;
    for (int i = threadIdx.x; i < HW_/4; i += 256) {
        float4 v = row[i];
        v.x = fmaxf((v.x - mu)*rstd, 0.f);
        v.y = fmaxf((v.y - mu)*rstd, 0.f);
        v.z = fmaxf((v.z - mu)*rstd, 0.f);
        v.w = fmaxf((v.w - mu)*rstd, 0.f);
        row[i] = v;
    }
}

// ---------------- launch ----------------
extern "C" void kernel_launch(void* const* d_in, const int* in_sizes, int n_in,
                              void* d_out, int out_size) {
    (void)in_sizes; (void)n_in; (void)out_size;
    const float* x     = (const float*)d_in[0];
    const float* dw_w  = (const float*)d_in[1];
    const float* dw_b  = (const float*)d_in[2];
    const float* bn_g  = (const float*)d_in[3];
    const float* bn_b  = (const float*)d_in[4];
    const float* bn_m  = (const float*)d_in[5];
    const float* bn_v  = (const float*)d_in[6];
    const float* pw_w  = (const float*)d_in[7];
    const float* pw_b  = (const float*)d_in[8];
    const float* dcn_w = (const float*)d_in[9];
    // d_in[10] = dcn_b: exactly cancelled by the instance norm -> unused.
    float* out = (float*)d_out;

    cudaFuncSetAttribute(k_main, cudaFuncAttributeMaxDynamicSharedMemorySize, SMEM_BYTES);

    k_transpose<<<dim3((W_/32)*(C_/32), H_, B_), dim3(32, 8)>>>(x);
    k_wprep<<<(J_*O_)/256, 256>>>(dcn_w);
    k_offsets<<<(B_*HW_)/4, 256>>>(dw_w, dw_b, bn_g, bn_b, bn_m, bn_v, pw_w, pw_b);
    k_main<<<(B_*HW_)/TP, 256, SMEM_BYTES>>>(out);
    k_inorm<<<B_*O_, 256>>>(out);
}

// round 3
// speedup vs baseline: 2.1902x; 2.1902x over previous
#include <cuda_runtime.h>

#define B_   2
#define C_   64
#define H_   192
#define W_   192
#define HW_  (H_*W_)
#define O_   64
#define K_   9
#define J_   576          // C_*K_
#define EPS_ 1e-5f

// ---------------- scratch (no allocations allowed) ----------------
__device__ float g_xnhwc[B_*HW_*C_];   // x transposed to [B][H][W][C]
__device__ float g_off[B_*HW_*27];     // per pixel: dy[9], dx[9], mask[9]
__device__ float g_wt[J_*O_];          // dcn_w paired: [j][32 float2] = (W[j][i], W[j][i+32])

// ---------------- kernel 0: NCHW -> NHWC transpose ----------------
__global__ void k_transpose(const float* __restrict__ x) {
    __shared__ float t[32][33];
    int xt = blockIdx.x % (W_/32);
    int ct = blockIdx.x / (W_/32);
    int y  = blockIdx.y, b = blockIdx.z;
    int tx = threadIdx.x, ty = threadIdx.y;
#pragma unroll
    for (int i = 0; i < 4; i++) {
        int c  = ct*32 + ty + i*8;
        int xx = xt*32 + tx;
        t[ty + i*8][tx] = x[((b*C_ + c)*H_ + y)*W_ + xx];
    }
    __syncthreads();
#pragma unroll
    for (int i = 0; i < 4; i++) {
        int xx = xt*32 + ty + i*8;
        int c  = ct*32 + tx;
        g_xnhwc[(((b*H_ + y)*W_ + xx) << 6) + c] = t[tx][ty + i*8];
    }
}

// ------ kernel 1: dcn_w -> [j][pair(i)] with pair = (o=i, o=i+32) ------
__global__ void k_wprep(const float* __restrict__ dcn_w) {
    int t = blockIdx.x*256 + threadIdx.x;     // dest index
    if (t < J_*O_) {
        int j    = t >> 6;
        int s    = t & 63;
        int i    = s >> 1;
        int half = s & 1;
        int o    = i + half*32;
        int c    = j & 63;
        int k    = j >> 6;
        g_wt[t] = dcn_w[o*J_ + c*K_ + k];
    }
}

// ------- kernel 2: dwconv + BN + ReLU + 1x1 -> offsets / mask -------
// 32 pixels (one row segment) per block, 256 threads.
__global__ void __launch_bounds__(256) k_offsets(
    const float* __restrict__ dw_w, const float* __restrict__ dw_b,
    const float* __restrict__ bn_g, const float* __restrict__ bn_b,
    const float* __restrict__ bn_m, const float* __restrict__ bn_v,
    const float* __restrict__ pw_w, const float* __restrict__ pw_b)
{
    __shared__ float xt[3*34*64];      // x neighborhood [row 0..2][col 0..33][c]
    __shared__ float hs[32*64];        // h[p][c]
    __shared__ float4 ws[16*27];       // pw_w packed: ws[i4*27+o] = pw_w[o][4*i4..+3]
    __shared__ float pb[27];

    int tid = threadIdx.x;
    int gp0 = blockIdx.x * 32;
    int b   = gp0 / HW_;
    int rem = gp0 % HW_;
    int y   = rem / W_;
    int x0  = rem % W_;

    // ---- load x neighborhood (3 rows x 34 cols x 64 ch), zero-fill OOB ----
    for (int e4 = tid; e4 < 3*34*16; e4 += 256) {
        int c4 = e4 & 15;
        int t2 = e4 >> 4;
        int xi = t2 % 34;
        int r  = t2 / 34;
        int yy = y - 1 + r;
        int xx = x0 - 1 + xi;
        float4 v = make_float4(0.f, 0.f, 0.f, 0.f);
        if ((unsigned)yy < H_ && (unsigned)xx < W_)
            v = *(const float4*)(g_xnhwc + (((b*H_ + yy)*W_ + xx) << 6) + c4*4);
        ((float4*)xt)[e4] = v;
    }
    // ---- load packed pw_w + bias ----
    for (int e = tid; e < 16*27; e += 256) {
        int o  = e % 27;
        int i4 = e / 27;
        const float* src = pw_w + o*64 + i4*4;
        ws[e] = make_float4(src[0], src[1], src[2], src[3]);
    }
    if (tid < 27) pb[tid] = pw_b[tid];
    __syncthreads();

    // ---- dwconv + BN + ReLU into hs[p][c] ----
#pragma unroll
    for (int i = 0; i < 8; i++) {
        int e = tid + i*256;
        int c = e & 63;
        int p = e >> 6;
        float acc = 0.f;
#pragma unroll
        for (int ky = 0; ky < 3; ky++) {
#pragma unroll
            for (int kx = 0; kx < 3; kx++) {
                acc += dw_w[c*9 + ky*3 + kx] * xt[(ky*34 + (p + kx))*64 + c];
            }
        }
        float s = bn_g[c] * rsqrtf(bn_v[c] + EPS_);
        hs[e] = fmaxf((acc + dw_b[c] - bn_m[c]) * s + bn_b[c], 0.f);
    }
    __syncthreads();

    // ---- pointwise 1x1: om[p][o], o in 0..26 ----
    for (int e = tid; e < 32*27; e += 256) {
        int p = e / 27;
        int o = e - p*27;
        float om = pb[o];
        const float4* hv = (const float4*)(hs + p*64);
#pragma unroll
        for (int i4 = 0; i4 < 16; i4++) {
            float4 h4 = hv[i4];
            float4 w4 = ws[i4*27 + o];
            om += h4.x*w4.x + h4.y*w4.y + h4.z*w4.z + h4.w*w4.w;
        }
        float* ob = g_off + (gp0 + p)*27;
        if (o < 18) {
            // output channel = k*2 + d; d==0 -> dy (slot k), d==1 -> dx (slot 9+k)
            ob[(o & 1)*9 + (o >> 1)] = om;
        } else {
            ob[o] = 1.f / (1.f + expf(-om));   // mask slot 18..26
        }
    }
}

// ------- kernel 3: deformable gather + 64x576 projection -------
#define TP 32
// smem: val[32][576] + double-buffered W tiles (2 x 2048 floats)
#define SMEM_FLOATS (TP*J_ + 2*2048)
#define SMEM_BYTES  (SMEM_FLOATS*4)

__global__ void __launch_bounds__(256) k_main(float* __restrict__ out) {
    extern __shared__ __align__(16) float sm[];
    float* val_s = sm;                 // [32][576]
    float* bufA  = sm + TP*J_;         // 2048 floats
    float* bufB  = bufA + 2048;        // 2048 floats

    int tid  = threadIdx.x;
    int gp0  = blockIdx.x * TP;
    int b    = gp0 / HW_;
    int rem0 = gp0 % HW_;
    int y    = rem0 / W_;              // one row per block (W % 32 == 0)
    int x0   = rem0 % W_;

    // ---------- gather phase: build val[p][k*64+c] ----------
    {
        int p  = tid >> 3;             // pixel 0..31
        int c8 = (tid & 7) << 3;       // channel base, 8 channels per thread
        int xx = x0 + p;
        const float* ob = g_off + (gp0 + p)*27;
#pragma unroll
        for (int k = 0; k < 9; k++) {
            float dy = ob[k], dx = ob[9+k], m = ob[18+k];
            float py = (float)(y  + k/3 - 1) + dy;
            float px = (float)(xx + k%3 - 1) + dx;
            float fy0 = floorf(py), fx0 = floorf(px);
            float wy1 = py - fy0,   wx1 = px - fx0;
            float wy0 = 1.f - wy1,  wx0 = 1.f - wx1;
            int   iy  = (int)fy0,   ix  = (int)fx0;

            float wts[4] = { wy0*wx0, wy0*wx1, wy1*wx0, wy1*wx1 };
            int   ys[4]  = { iy, iy, iy+1, iy+1 };
            int   xs[4]  = { ix, ix+1, ix, ix+1 };

            float4 a0 = make_float4(0.f,0.f,0.f,0.f);
            float4 a1 = make_float4(0.f,0.f,0.f,0.f);
#pragma unroll
            for (int cn = 0; cn < 4; cn++) {
                if ((unsigned)ys[cn] < H_ && (unsigned)xs[cn] < W_) {
                    const float4* src = (const float4*)
                        (g_xnhwc + (((b*H_ + ys[cn])*W_ + xs[cn]) << 6) + c8);
                    float4 v0 = src[0], v1 = src[1];
                    float w = wts[cn];
                    a0.x += w*v0.x; a0.y += w*v0.y; a0.z += w*v0.z; a0.w += w*v0.w;
                    a1.x += w*v1.x; a1.y += w*v1.y; a1.z += w*v1.z; a1.w += w*v1.w;
                }
            }
            a0.x *= m; a0.y *= m; a0.z *= m; a0.w *= m;
            a1.x *= m; a1.y *= m; a1.z *= m; a1.w *= m;
            float4* dst = (float4*)(val_s + p*J_ + k*64 + c8);
            dst[0] = a0; dst[1] = a1;
        }
    }

    // prefetch W tile 0 (no sync needed w.r.t. gather: disjoint smem)
    {
        float4* wdst = (float4*)bufA;
        const float4* wsrc = (const float4*)g_wt;
        wdst[tid] = wsrc[tid]; wdst[tid + 256] = wsrc[tid + 256];
    }
    __syncthreads();

    // ---------- GEMM: out[p][o] = sum_j val[p][j] * W[j][o] ----------
    int lane = tid & 31;
    int warp = tid >> 5;
    int p0   = warp << 2;              // 4 pixels per warp; lane -> o pair (lane, lane+32)
    float acc00=0.f, acc01=0.f, acc10=0.f, acc11=0.f;
    float acc20=0.f, acc21=0.f, acc30=0.f, acc31=0.f;

    const float* vb0 = val_s + (p0+0)*J_;
    const float* vb1 = val_s + (p0+1)*J_;
    const float* vb2 = val_s + (p0+2)*J_;
    const float* vb3 = val_s + (p0+3)*J_;

#pragma unroll 1
    for (int jt = 0; jt < 18; jt++) {
        const float* cur = (jt & 1) ? bufB : bufA;
        float*       nxt = (jt & 1) ? bufA : bufB;
        if (jt < 17) {
            float4* wdst = (float4*)nxt;
            const float4* wsrc = (const float4*)(g_wt + (jt+1)*2048);
            wdst[tid] = wsrc[tid]; wdst[tid + 256] = wsrc[tid + 256];
        }

        const float* vt0 = vb0 + jt*32;
        const float* vt1 = vb1 + jt*32;
        const float* vt2 = vb2 + jt*32;
        const float* vt3 = vb3 + jt*32;
        const float2* w2 = (const float2*)cur;
#pragma unroll
        for (int q = 0; q < 8; q++) {
            float4 v0 = *(const float4*)(vt0 + q*4);
            float4 v1 = *(const float4*)(vt1 + q*4);
            float4 v2 = *(const float4*)(vt2 + q*4);
            float4 v3 = *(const float4*)(vt3 + q*4);
            const float2* wq = w2 + q*128 + lane;   // (q*4+u)*32 + lane
            {   float2 w = wq[0];
                acc00 += v0.x*w.x; acc01 += v0.x*w.y;
                acc10 += v1.x*w.x; acc11 += v1.x*w.y;
                acc20 += v2.x*w.x; acc21 += v2.x*w.y;
                acc30 += v3.x*w.x; acc31 += v3.x*w.y; }
            {   float2 w = wq[32];
                acc00 += v0.y*w.x; acc01 += v0.y*w.y;
                acc10 += v1.y*w.x; acc11 += v1.y*w.y;
                acc20 += v2.y*w.x; acc21 += v2.y*w.y;
                acc30 += v3.y*w.x; acc31 += v3.y*w.y; }
            {   float2 w = wq[64];
                acc00 += v0.z*w.x; acc01 += v0.z*w.y;
                acc10 += v1.z*w.x; acc11 += v1.z*w.y;
                acc20 += v2.z*w.x; acc21 += v2.z*w.y;
                acc30 += v3.z*w.x; acc31 += v3.z*w.y; }
            {   float2 w = wq[96];
                acc00 += v0.w*w.x; acc01 += v0.w*w.y;
                acc10 += v1.w*w.x; acc11 += v1.w*w.y;
                acc20 += v2.w*w.x; acc21 += v2.w*w.y;
                acc30 += v3.w*w.x; acc31 += v3.w*w.y; }
        }
        __syncthreads();
    }

    // stage outputs [o][p] (stride 33, conflict-free), then coalesced store
    float* stg = bufA;                 // 64*33 = 2112 <= 4096 floats available
    {
        int o0 = lane, o1 = lane + 32;
        stg[o0*33 + p0+0] = acc00; stg[o0*33 + p0+1] = acc10;
        stg[o0*33 + p0+2] = acc20; stg[o0*33 + p0+3] = acc30;
        stg[o1*33 + p0+0] = acc01; stg[o1*33 + p0+1] = acc11;
        stg[o1*33 + p0+2] = acc21; stg[o1*33 + p0+3] = acc31;
    }
    __syncthreads();
#pragma unroll
    for (int r = 0; r < 8; r++) {
        int q = r*256 + tid;
        int o = q >> 5;
        int p = q & 31;
        out[(b*O_ + o)*HW_ + rem0 + p] = stg[o*33 + p];
    }
}

// ------- kernel 4: per-(b,o) instance norm + ReLU, in-place -------
__global__ void __launch_bounds__(256) k_inorm(float* __restrict__ out) {
    int bo = blockIdx.x;
    float4* row = (float4*)(out + bo*HW_);
    float s = 0.f, ss = 0.f;
    for (int i = threadIdx.x; i < HW_/4; i += 256) {
        float4 v = row[i];
        s  += v.x + v.y + v.z + v.w;
        ss += v.x*v.x + v.y*v.y + v.z*v.z + v.w*v.w;
    }
#pragma unroll
    for (int off = 16; off; off >>= 1) {
        s  += __shfl_xor_sync(~0u, s,  off);
        ss += __shfl_xor_sync(~0u, ss, off);
    }
    __shared__ float rs[8], rss[8];
    __shared__ float mu_s, rstd_s;
    if ((threadIdx.x & 31) == 0) { rs[threadIdx.x>>5] = s; rss[threadIdx.x>>5] = ss; }
    __syncthreads();
    if (threadIdx.x == 0) {
        float S = 0.f, SS = 0.f;
#pragma unroll
        for (int i = 0; i < 8; i++) { S += rs[i]; SS += rss[i]; }
        float mu  = S / (float)HW_;
        float var = SS / (float)HW_ - mu*mu;
        mu_s = mu;
        rstd_s = rsqrtf(var + EPS_);
    }
    __syncthreads();
    float mu = mu_s, rstd = rstd_s;
    for (int i = threadIdx.x; i < HW_/4; i += 256) {
        float4 v = row[i];
        v.x = fmaxf((v.x - mu)*rstd, 0.f);
        v.y = fmaxf((v.y - mu)*rstd, 0.f);
        v.z = fmaxf((v.z - mu)*rstd, 0.f);
        v.w = fmaxf((v.w - mu)*rstd, 0.f);
        row[i] = v;
    }
}

// ---------------- launch ----------------
extern "C" void kernel_launch(void* const* d_in, const int* in_sizes, int n_in,
                              void* d_out, int out_size) {
    (void)in_sizes; (void)n_in; (void)out_size;
    const float* x     = (const float*)d_in[0];
    const float* dw_w  = (const float*)d_in[1];
    const float* dw_b  = (const float*)d_in[2];
    const float* bn_g  = (const float*)d_in[3];
    const float* bn_b  = (const float*)d_in[4];
    const float* bn_m  = (const float*)d_in[5];
    const float* bn_v  = (const float*)d_in[6];
    const float* pw_w  = (const float*)d_in[7];
    const float* pw_b  = (const float*)d_in[8];
    const float* dcn_w = (const float*)d_in[9];
    // d_in[10] = dcn_b: exactly cancelled by the instance norm -> unused.
    float* out = (float*)d_out;

    cudaFuncSetAttribute(k_main, cudaFuncAttributeMaxDynamicSharedMemorySize, SMEM_BYTES);

    k_transpose<<<dim3((W_/32)*(C_/32), H_, B_), dim3(32, 8)>>>(x);
    k_wprep<<<(J_*O_ + 255)/256, 256>>>(dcn_w);
    k_offsets<<<(B_*HW_)/32, 256>>>(dw_w, dw_b, bn_g, bn_b, bn_m, bn_v, pw_w, pw_b);
    k_main<<<(B_*HW_)/TP, 256, SMEM_BYTES>>>(out);
    k_inorm<<<B_*O_, 256>>>(out);
}